// round 3
// baseline (speedup 1.0000x reference)
#include <cuda_runtime.h>
#include <cuda_fp16.h>

// Problem constants
#define NB 2
#define NC 128
#define NS 2048
#define MPX 65536                // Nz*Nx pixels per batch
#define NKK 4

#define THREADS 256
#define PXT 8                    // pixels per thread
#define TILE_PX (THREADS * PXT)  // 2048 pixels per CTA
#define TILES (MPX / TILE_PX)    // 32 tiles per batch

#define SPLIT 4
#define CPC (NC / SPLIT)         // 32 channels per CTA

// fp16 rf row = NS * 4 halves = 16KB per channel; double buffered
#define SMEM_BYTES (2 * NS * 8 + CPC * 3 * 4)

// Static device scratch (no allocations allowed)
__device__ __half g_rf16[(size_t)NB * NC * NS * NKK];           // 4.2 MB
__device__ float  g_part[(size_t)SPLIT * NB * MPX * NKK];       // 8.4 MB

__device__ __forceinline__ unsigned smem_u32(const void* p) {
    unsigned a;
    asm("{ .reg .u64 t; cvta.to.shared.u64 t, %1; cvt.u32.u64 %0, t; }"
        : "=r"(a) : "l"(p));
    return a;
}
__device__ __forceinline__ void cp16(unsigned s, const void* g) {
    asm volatile("cp.async.cg.shared.global [%0], [%1], 16;" :: "r"(s), "l"(g));
}
__device__ __forceinline__ void cp_commit() {
    asm volatile("cp.async.commit_group;");
}
template <int N>
__device__ __forceinline__ void cp_wait() {
    asm volatile("cp.async.wait_group %0;" :: "n"(N));
}

// ---------------------------------------------------------------------------
// Kernel 1: convert rf fp32 -> fp16 scratch. 4 rows per thread, MLP=4.
// ---------------------------------------------------------------------------
__global__ void convert_rf_kernel(const float4* __restrict__ rf4) {
    int t = blockIdx.x * blockDim.x + threadIdx.x;   // NB*NC*NS/4 threads
    int idx = t * 4;
    float4 v0 = rf4[idx + 0];
    float4 v1 = rf4[idx + 1];
    float4 v2 = rf4[idx + 2];
    float4 v3 = rf4[idx + 3];
    uint4 o0, o1;
    __half2 h;
    h = __floats2half2_rn(v0.x, v0.y); o0.x = *reinterpret_cast<unsigned*>(&h);
    h = __floats2half2_rn(v0.z, v0.w); o0.y = *reinterpret_cast<unsigned*>(&h);
    h = __floats2half2_rn(v1.x, v1.y); o0.z = *reinterpret_cast<unsigned*>(&h);
    h = __floats2half2_rn(v1.z, v1.w); o0.w = *reinterpret_cast<unsigned*>(&h);
    h = __floats2half2_rn(v2.x, v2.y); o1.x = *reinterpret_cast<unsigned*>(&h);
    h = __floats2half2_rn(v2.z, v2.w); o1.y = *reinterpret_cast<unsigned*>(&h);
    h = __floats2half2_rn(v3.x, v3.y); o1.z = *reinterpret_cast<unsigned*>(&h);
    h = __floats2half2_rn(v3.z, v3.w); o1.w = *reinterpret_cast<unsigned*>(&h);
    uint4* dst = reinterpret_cast<uint4*>(g_rf16) + t * 2;
    dst[0] = o0;
    dst[1] = o1;
}

// ---------------------------------------------------------------------------
// Kernel 2: main DAS beamform over a channel slice, writes partial sums.
// ---------------------------------------------------------------------------
extern __shared__ char smem_raw[];

__global__ __launch_bounds__(THREADS, 2)
void das_beamform_kernel(const float* __restrict__ g,
                         const float* __restrict__ pr,
                         const float* __restrict__ p)
{
    uint2* sbuf = reinterpret_cast<uint2*>(smem_raw);             // [2][NS]
    float* s_pr = reinterpret_cast<float*>(smem_raw + 2 * NS * 8);

    const int b     = blockIdx.y;
    const int sp    = blockIdx.z;
    const int tile0 = blockIdx.x * TILE_PX;
    const int tid   = threadIdx.x;
    const int c0    = sp * CPC;

    const float c0v = p[b * 4 + 0];
    const float fs  = p[b * 4 + 1];
    const float t0  = p[b * 4 + 2];
    const float scale = fs / c0v;
    const float toff  = t0 * scale;

    // Cache this slice's receiver positions
    if (tid < CPC * 3)
        s_pr[tid] = pr[((size_t)b * NC + c0) * 3 + tid];

    float gx[PXT], gy[PXT], gz[PXT], base[PXT];
    float4 acc[PXT];
#pragma unroll
    for (int q = 0; q < PXT; q++) {
        int m = tile0 + tid + q * THREADS;
        const float* gp = g + ((size_t)b * MPX + m) * 3;
        gx[q] = gp[0];
        gy[q] = gp[1];
        gz[q] = gp[2];
        base[q] = fmaf(scale, gz[q], toff);
        acc[q] = make_float4(0.f, 0.f, 0.f, 0.f);
    }

    // fp16 rf rows for this (batch, slice): 16B chunks, NS/2 per channel row
    const uint4* rfb = reinterpret_cast<const uint4*>(g_rf16) +
                       ((size_t)b * NC + c0) * (NS / 2);

    // Preload channel c0 into buffer 0 (1024 chunks of 16B)
    {
        const uint4* src = rfb;
        unsigned dst = smem_u32(sbuf);
#pragma unroll
        for (int j = 0; j < (NS / 2) / THREADS; j++)
            cp16(dst + (tid + j * THREADS) * 16, src + tid + j * THREADS);
        cp_commit();
    }

    for (int cc = 0; cc < CPC; cc++) {
        __syncthreads();   // readers of buffer (cc+1)&1 from iter cc-1 are done

        if (cc + 1 < CPC) {
            const uint4* src = rfb + (size_t)(cc + 1) * (NS / 2);
            unsigned dst = smem_u32(sbuf + ((cc + 1) & 1) * NS);
#pragma unroll
            for (int j = 0; j < (NS / 2) / THREADS; j++)
                cp16(dst + (tid + j * THREADS) * 16, src + tid + j * THREADS);
            cp_commit();
            cp_wait<1>();   // channel cc's fill group complete
        } else {
            cp_wait<0>();
        }
        __syncthreads();

        const uint2* buf = sbuf + (cc & 1) * NS;
        const float prx = s_pr[cc * 3 + 0];
        const float pry = s_pr[cc * 3 + 1];
        const float prz = s_pr[cc * 3 + 2];

#pragma unroll
        for (int q = 0; q < PXT; q++) {
            float dx = gx[q] - prx;
            float dy = gy[q] - pry;
            float dz = gz[q] - prz;
            float d2 = fmaf(dx, dx, fmaf(dy, dy, dz * dz));
            float dr = sqrtf(d2);
            float s  = fmaf(scale, dr, base[q]);
            s = fminf(fmaxf(s, 0.0f), (float)(NS - 1));
            int i0 = (int)s;
            i0 = min(i0, NS - 2);
            float w = s - (float)i0;

            uint2 r0 = buf[i0];
            uint2 r1 = buf[i0 + 1];
            float2 a0 = __half22float2(*reinterpret_cast<__half2*>(&r0.x));
            float2 b0 = __half22float2(*reinterpret_cast<__half2*>(&r0.y));
            float2 a1 = __half22float2(*reinterpret_cast<__half2*>(&r1.x));
            float2 b1 = __half22float2(*reinterpret_cast<__half2*>(&r1.y));

            acc[q].x = fmaf(w, a1.x - a0.x, acc[q].x + a0.x);
            acc[q].y = fmaf(w, a1.y - a0.y, acc[q].y + a0.y);
            acc[q].z = fmaf(w, b1.x - b0.x, acc[q].z + b0.x);
            acc[q].w = fmaf(w, b1.y - b0.y, acc[q].w + b0.y);
        }
    }

    float4* pp = reinterpret_cast<float4*>(g_part) +
                 ((size_t)sp * NB + b) * MPX + tile0;
#pragma unroll
    for (int q = 0; q < PXT; q++)
        pp[tid + q * THREADS] = acc[q];
}

// ---------------------------------------------------------------------------
// Kernel 3: reduce SPLIT partials into the output.
// ---------------------------------------------------------------------------
__global__ void reduce_kernel(float4* __restrict__ out4) {
    int i = blockIdx.x * blockDim.x + threadIdx.x;   // over NB*MPX float4s
    const size_t stride = (size_t)NB * MPX;
    const float4* pp = reinterpret_cast<const float4*>(g_part);
    float4 a = pp[i];
    float4 b = pp[i + stride];
    float4 c = pp[i + 2 * stride];
    float4 d = pp[i + 3 * stride];
    float4 r;
    r.x = (a.x + b.x) + (c.x + d.x);
    r.y = (a.y + b.y) + (c.y + d.y);
    r.z = (a.z + b.z) + (c.z + d.z);
    r.w = (a.w + b.w) + (c.w + d.w);
    out4[i] = r;
}

extern "C" void kernel_launch(void* const* d_in, const int* in_sizes, int n_in,
                              void* d_out, int out_size)
{
    const float* rf = (const float*)d_in[0];   // [B, Nc, Ns, K]
    const float* g  = (const float*)d_in[1];   // [B, Nz, Nx, 3]
    const float* pr = (const float*)d_in[2];   // [B, Nc, 3]
    const float* p  = (const float*)d_in[3];   // [B, 4]
    float* out = (float*)d_out;                // [B, Nz, Nx, K]

    cudaFuncSetAttribute(das_beamform_kernel,
                         cudaFuncAttributeMaxDynamicSharedMemorySize, SMEM_BYTES);

    // 1) convert rf to fp16 scratch (4 sample-rows per thread)
    int rows = NB * NC * NS;   // 524288
    convert_rf_kernel<<<rows / 4 / THREADS, THREADS>>>((const float4*)rf);

    // 2) beamform per (tile, batch, channel-slice)
    dim3 grid(TILES, NB, SPLIT);
    das_beamform_kernel<<<grid, THREADS, SMEM_BYTES>>>(g, pr, p);

    // 3) reduce partials
    int n4 = NB * MPX;         // 131072 float4s
    reduce_kernel<<<n4 / THREADS, THREADS>>>((float4*)out);
}

// round 6
// speedup vs baseline: 1.0047x; 1.0047x over previous
#include <cuda_runtime.h>
#include <cuda_fp16.h>

// Problem constants
#define NB 2
#define NC 128
#define NS 2048
#define MPX 65536                // Nz*Nx pixels per batch
#define NKK 4

#define THREADS 256
#define PXT 4                    // pixels per thread
#define TILE_PX (THREADS * PXT)  // 1024 pixels per CTA
#define TILES (MPX / TILE_PX)    // 64 tiles per batch

#define SPLIT 8
#define CPC (NC / SPLIT)         // 16 channels per CTA

// fp16 rf row = NS * 4 halves = 16KB per channel; double buffered
#define SMEM_BYTES (2 * NS * 8 + CPC * 3 * 4)

// Static device scratch (no allocations allowed)
__device__ __half g_rf16[(size_t)NB * NC * NS * NKK];           // 4.2 MB
__device__ float  g_part[(size_t)SPLIT * NB * MPX * NKK];       // 16.8 MB

__device__ __forceinline__ unsigned smem_u32(const void* p) {
    unsigned a;
    asm("{ .reg .u64 t; cvta.to.shared.u64 t, %1; cvt.u32.u64 %0, t; }"
        : "=r"(a) : "l"(p));
    return a;
}
__device__ __forceinline__ void cp16(unsigned s, const void* g) {
    asm volatile("cp.async.cg.shared.global [%0], [%1], 16;" :: "r"(s), "l"(g));
}
__device__ __forceinline__ void cp_commit() {
    asm volatile("cp.async.commit_group;");
}
template <int N>
__device__ __forceinline__ void cp_wait() {
    asm volatile("cp.async.wait_group %0;" :: "n"(N));
}

// ---------------------------------------------------------------------------
// Kernel 1: convert rf fp32 -> fp16 scratch. 2 rows per thread.
// ---------------------------------------------------------------------------
__global__ void convert_rf_kernel(const float4* __restrict__ rf4) {
    int t = blockIdx.x * blockDim.x + threadIdx.x;   // NB*NC*NS/2 threads
    int idx = t * 2;
    float4 v0 = rf4[idx + 0];
    float4 v1 = rf4[idx + 1];
    uint4 o;
    __half2 h;
    h = __floats2half2_rn(v0.x, v0.y); o.x = *reinterpret_cast<unsigned*>(&h);
    h = __floats2half2_rn(v0.z, v0.w); o.y = *reinterpret_cast<unsigned*>(&h);
    h = __floats2half2_rn(v1.x, v1.y); o.z = *reinterpret_cast<unsigned*>(&h);
    h = __floats2half2_rn(v1.z, v1.w); o.w = *reinterpret_cast<unsigned*>(&h);
    reinterpret_cast<uint4*>(g_rf16)[t] = o;
}

// ---------------------------------------------------------------------------
// Kernel 2: main DAS beamform over a channel slice, writes partial sums.
// ---------------------------------------------------------------------------
extern __shared__ char smem_raw[];

__global__ __launch_bounds__(THREADS, 6)
void das_beamform_kernel(const float* __restrict__ g,
                         const float* __restrict__ pr,
                         const float* __restrict__ p)
{
    uint2* sbuf = reinterpret_cast<uint2*>(smem_raw);             // [2][NS]
    float* s_pr = reinterpret_cast<float*>(smem_raw + 2 * NS * 8);

    const int b     = blockIdx.y;
    const int sp    = blockIdx.z;
    const int tile0 = blockIdx.x * TILE_PX;
    const int tid   = threadIdx.x;
    const int c0    = sp * CPC;

    const float c0v = p[b * 4 + 0];
    const float fs  = p[b * 4 + 1];
    const float t0  = p[b * 4 + 2];
    const float scale = fs / c0v;
    const float toff  = t0 * scale;

    // Cache this slice's receiver positions
    if (tid < CPC * 3)
        s_pr[tid] = pr[((size_t)b * NC + c0) * 3 + tid];

    float gx[PXT], gy[PXT], gz[PXT], base[PXT];
    float4 acc[PXT];
#pragma unroll
    for (int q = 0; q < PXT; q++) {
        int m = tile0 + tid + q * THREADS;
        const float* gp = g + ((size_t)b * MPX + m) * 3;
        gx[q] = gp[0];
        gy[q] = gp[1];
        gz[q] = gp[2];
        base[q] = fmaf(scale, gz[q], toff);
        acc[q] = make_float4(0.f, 0.f, 0.f, 0.f);
    }

    // fp16 rf rows for this (batch, slice): 16B chunks, NS/2 per channel row
    const uint4* rfb = reinterpret_cast<const uint4*>(g_rf16) +
                       ((size_t)b * NC + c0) * (NS / 2);

    // Preload channel c0 into buffer 0 (1024 chunks of 16B)
    {
        const uint4* src = rfb;
        unsigned dst = smem_u32(sbuf);
#pragma unroll
        for (int j = 0; j < (NS / 2) / THREADS; j++)
            cp16(dst + (tid + j * THREADS) * 16, src + tid + j * THREADS);
        cp_commit();
    }

    for (int cc = 0; cc < CPC; cc++) {
        __syncthreads();   // readers of buffer (cc+1)&1 from iter cc-1 are done

        if (cc + 1 < CPC) {
            const uint4* src = rfb + (size_t)(cc + 1) * (NS / 2);
            unsigned dst = smem_u32(sbuf + ((cc + 1) & 1) * NS);
#pragma unroll
            for (int j = 0; j < (NS / 2) / THREADS; j++)
                cp16(dst + (tid + j * THREADS) * 16, src + tid + j * THREADS);
            cp_commit();
            cp_wait<1>();   // channel cc's fill group complete
        } else {
            cp_wait<0>();
        }
        __syncthreads();

        const uint2* buf = sbuf + (cc & 1) * NS;
        const float prx = s_pr[cc * 3 + 0];
        const float pry = s_pr[cc * 3 + 1];
        const float prz = s_pr[cc * 3 + 2];

#pragma unroll
        for (int q = 0; q < PXT; q++) {
            float dx = gx[q] - prx;
            float dy = gy[q] - pry;
            float dz = gz[q] - prz;
            float d2 = fmaf(dx, dx, fmaf(dy, dy, dz * dz));
            float dr = sqrtf(d2);
            float s  = fmaf(scale, dr, base[q]);
            s = fminf(fmaxf(s, 0.0f), (float)(NS - 1));
            int i0 = (int)s;
            i0 = min(i0, NS - 2);
            float w = s - (float)i0;

            uint2 r0 = buf[i0];
            uint2 r1 = buf[i0 + 1];
            float2 a0 = __half22float2(*reinterpret_cast<__half2*>(&r0.x));
            float2 b0 = __half22float2(*reinterpret_cast<__half2*>(&r0.y));
            float2 a1 = __half22float2(*reinterpret_cast<__half2*>(&r1.x));
            float2 b1 = __half22float2(*reinterpret_cast<__half2*>(&r1.y));

            acc[q].x = fmaf(w, a1.x - a0.x, acc[q].x + a0.x);
            acc[q].y = fmaf(w, a1.y - a0.y, acc[q].y + a0.y);
            acc[q].z = fmaf(w, b1.x - b0.x, acc[q].z + b0.x);
            acc[q].w = fmaf(w, b1.y - b0.y, acc[q].w + b0.y);
        }
    }

    float4* pp = reinterpret_cast<float4*>(g_part) +
                 ((size_t)sp * NB + b) * MPX + tile0;
#pragma unroll
    for (int q = 0; q < PXT; q++)
        pp[tid + q * THREADS] = acc[q];
}

// ---------------------------------------------------------------------------
// Kernel 3: reduce SPLIT partials into the output.
// ---------------------------------------------------------------------------
__global__ void reduce_kernel(float4* __restrict__ out4) {
    int i = blockIdx.x * blockDim.x + threadIdx.x;   // over NB*MPX float4s
    const size_t stride = (size_t)NB * MPX;
    const float4* pp = reinterpret_cast<const float4*>(g_part);
    float4 r = make_float4(0.f, 0.f, 0.f, 0.f);
#pragma unroll
    for (int s = 0; s < SPLIT; s++) {
        float4 v = pp[i + s * stride];
        r.x += v.x; r.y += v.y; r.z += v.z; r.w += v.w;
    }
    out4[i] = r;
}

extern "C" void kernel_launch(void* const* d_in, const int* in_sizes, int n_in,
                              void* d_out, int out_size)
{
    const float* rf = (const float*)d_in[0];   // [B, Nc, Ns, K]
    const float* g  = (const float*)d_in[1];   // [B, Nz, Nx, 3]
    const float* pr = (const float*)d_in[2];   // [B, Nc, 3]
    const float* p  = (const float*)d_in[3];   // [B, 4]
    float* out = (float*)d_out;                // [B, Nz, Nx, K]

    cudaFuncSetAttribute(das_beamform_kernel,
                         cudaFuncAttributeMaxDynamicSharedMemorySize, SMEM_BYTES);

    // 1) convert rf to fp16 scratch (2 sample-rows per thread)
    int rows = NB * NC * NS;   // 524288
    convert_rf_kernel<<<rows / 2 / THREADS, THREADS>>>((const float4*)rf);

    // 2) beamform per (tile, batch, channel-slice)
    dim3 grid(TILES, NB, SPLIT);
    das_beamform_kernel<<<grid, THREADS, SMEM_BYTES>>>(g, pr, p);

    // 3) reduce partials
    int n4 = NB * MPX;         // 131072 float4s
    reduce_kernel<<<n4 / THREADS, THREADS>>>((float4*)out);
}

// round 7
// speedup vs baseline: 1.0499x; 1.0450x over previous
#include <cuda_runtime.h>
#include <cuda_fp16.h>

// Problem constants
#define NB 2
#define NC 128
#define NS 2048
#define MPX 65536                // Nz*Nx pixels per batch
#define NKK 4

#define THREADS 256
#define PXT 4                    // pixels per thread
#define TILE_PX (THREADS * PXT)  // 1024 pixels per CTA
#define TILES (MPX / TILE_PX)    // 64 tiles per batch

#define SPLIT 4
#define CPC (NC / SPLIT)         // 32 channels per CTA

#define NBUF 3                   // triple buffer
// fp16 rf row = NS * 4 halves = 16KB per channel
#define SMEM_BYTES (NBUF * NS * 8 + CPC * 3 * 4)

// Static device scratch (no allocations allowed)
__device__ __half g_rf16[(size_t)NB * NC * NS * NKK];           // 4.2 MB
__device__ float  g_part[(size_t)SPLIT * NB * MPX * NKK];       // 8.4 MB

__device__ __forceinline__ unsigned smem_u32(const void* p) {
    unsigned a;
    asm("{ .reg .u64 t; cvta.to.shared.u64 t, %1; cvt.u32.u64 %0, t; }"
        : "=r"(a) : "l"(p));
    return a;
}
__device__ __forceinline__ void cp16(unsigned s, const void* g) {
    asm volatile("cp.async.cg.shared.global [%0], [%1], 16;" :: "r"(s), "l"(g));
}
__device__ __forceinline__ void cp_commit() {
    asm volatile("cp.async.commit_group;");
}
template <int N>
__device__ __forceinline__ void cp_wait() {
    asm volatile("cp.async.wait_group %0;" :: "n"(N));
}

// ---------------------------------------------------------------------------
// Kernel 1: convert rf fp32 -> fp16 scratch. 2 rows per thread.
// ---------------------------------------------------------------------------
__global__ void convert_rf_kernel(const float4* __restrict__ rf4) {
    int t = blockIdx.x * blockDim.x + threadIdx.x;   // NB*NC*NS/2 threads
    int idx = t * 2;
    float4 v0 = rf4[idx + 0];
    float4 v1 = rf4[idx + 1];
    uint4 o;
    __half2 h;
    h = __floats2half2_rn(v0.x, v0.y); o.x = *reinterpret_cast<unsigned*>(&h);
    h = __floats2half2_rn(v0.z, v0.w); o.y = *reinterpret_cast<unsigned*>(&h);
    h = __floats2half2_rn(v1.x, v1.y); o.z = *reinterpret_cast<unsigned*>(&h);
    h = __floats2half2_rn(v1.z, v1.w); o.w = *reinterpret_cast<unsigned*>(&h);
    reinterpret_cast<uint4*>(g_rf16)[t] = o;
}

// ---------------------------------------------------------------------------
// Kernel 2: main DAS beamform over a channel slice, writes partial sums.
// ---------------------------------------------------------------------------
extern __shared__ char smem_raw[];

__global__ __launch_bounds__(THREADS, 4)
void das_beamform_kernel(const float* __restrict__ g,
                         const float* __restrict__ pr,
                         const float* __restrict__ p)
{
    uint2* sbuf = reinterpret_cast<uint2*>(smem_raw);                  // [NBUF][NS]
    float* s_pr = reinterpret_cast<float*>(smem_raw + NBUF * NS * 8);

    const int b     = blockIdx.y;
    const int sp    = blockIdx.z;
    const int tile0 = blockIdx.x * TILE_PX;
    const int tid   = threadIdx.x;
    const int c0    = sp * CPC;

    const float c0v = p[b * 4 + 0];
    const float fs  = p[b * 4 + 1];
    const float t0  = p[b * 4 + 2];
    const float scale = fs / c0v;
    const float toff  = t0 * scale;

    // Cache this slice's receiver positions
    if (tid < CPC * 3)
        s_pr[tid] = pr[((size_t)b * NC + c0) * 3 + tid];

    float gx[PXT], gy[PXT], gz[PXT], base[PXT];
    __half2 accA[PXT], accB[PXT];      // fp16 accumulators: (k0,k1) and (k2,k3)
#pragma unroll
    for (int q = 0; q < PXT; q++) {
        int m = tile0 + tid + q * THREADS;
        const float* gp = g + ((size_t)b * MPX + m) * 3;
        gx[q] = gp[0];
        gy[q] = gp[1];
        gz[q] = gp[2];
        base[q] = fmaf(scale, gz[q], toff);
        accA[q] = __half2half2(__ushort_as_half(0));
        accB[q] = __half2half2(__ushort_as_half(0));
    }

    // fp16 rf rows for this (batch, slice): 16B chunks, NS/2 per channel row
    const uint4* rfb = reinterpret_cast<const uint4*>(g_rf16) +
                       ((size_t)b * NC + c0) * (NS / 2);

    // Preload channels 0 and 1
#pragma unroll
    for (int pc = 0; pc < 2; pc++) {
        const uint4* src = rfb + (size_t)pc * (NS / 2);
        unsigned dst = smem_u32(sbuf + pc * NS);
#pragma unroll
        for (int j = 0; j < (NS / 2) / THREADS; j++)
            cp16(dst + (tid + j * THREADS) * 16, src + tid + j * THREADS);
        cp_commit();
    }

    for (int cc = 0; cc < CPC; cc++) {
        if (cc + 2 < CPC) cp_wait<1>();   // channel cc's fill group complete
        else              cp_wait<0>();
        __syncthreads();   // fills visible to all; readers of buf[(cc+2)%3] done

        if (cc + 2 < CPC) {
            const uint4* src = rfb + (size_t)(cc + 2) * (NS / 2);
            unsigned dst = smem_u32(sbuf + ((cc + 2) % NBUF) * NS);
#pragma unroll
            for (int j = 0; j < (NS / 2) / THREADS; j++)
                cp16(dst + (tid + j * THREADS) * 16, src + tid + j * THREADS);
            cp_commit();
        }

        const uint2* buf = sbuf + (cc % NBUF) * NS;
        const float prx = s_pr[cc * 3 + 0];
        const float pry = s_pr[cc * 3 + 1];
        const float prz = s_pr[cc * 3 + 2];

#pragma unroll
        for (int q = 0; q < PXT; q++) {
            float dx = gx[q] - prx;
            float dy = gy[q] - pry;
            float dz = gz[q] - prz;
            float d2 = fmaf(dx, dx, fmaf(dy, dy, dz * dz));
            float dr = sqrtf(d2);
            float s  = fmaf(scale, dr, base[q]);
            s = fminf(fmaxf(s, 0.0f), (float)(NS - 1));
            int i0 = (int)s;
            i0 = min(i0, NS - 2);
            float w = s - (float)i0;

            uint2 r0 = buf[i0];
            uint2 r1 = buf[i0 + 1];
            __half2 w2 = __half2half2(__float2half_rn(w));
            __half2 y0A = *reinterpret_cast<__half2*>(&r0.x);
            __half2 y0B = *reinterpret_cast<__half2*>(&r0.y);
            __half2 y1A = *reinterpret_cast<__half2*>(&r1.x);
            __half2 y1B = *reinterpret_cast<__half2*>(&r1.y);
            // acc += y0 + w*(y1-y0)
            accA[q] = __hadd2(accA[q], __hfma2(w2, __hsub2(y1A, y0A), y0A));
            accB[q] = __hadd2(accB[q], __hfma2(w2, __hsub2(y1B, y0B), y0B));
        }
    }

    float4* pp = reinterpret_cast<float4*>(g_part) +
                 ((size_t)sp * NB + b) * MPX + tile0;
#pragma unroll
    for (int q = 0; q < PXT; q++) {
        float2 a = __half22float2(accA[q]);
        float2 c = __half22float2(accB[q]);
        pp[tid + q * THREADS] = make_float4(a.x, a.y, c.x, c.y);
    }
}

// ---------------------------------------------------------------------------
// Kernel 3: reduce SPLIT partials into the output.
// ---------------------------------------------------------------------------
__global__ void reduce_kernel(float4* __restrict__ out4) {
    int i = blockIdx.x * blockDim.x + threadIdx.x;   // over NB*MPX float4s
    const size_t stride = (size_t)NB * MPX;
    const float4* pp = reinterpret_cast<const float4*>(g_part);
    float4 a = pp[i];
    float4 b = pp[i + stride];
    float4 c = pp[i + 2 * stride];
    float4 d = pp[i + 3 * stride];
    float4 r;
    r.x = (a.x + b.x) + (c.x + d.x);
    r.y = (a.y + b.y) + (c.y + d.y);
    r.z = (a.z + b.z) + (c.z + d.z);
    r.w = (a.w + b.w) + (c.w + d.w);
    out4[i] = r;
}

extern "C" void kernel_launch(void* const* d_in, const int* in_sizes, int n_in,
                              void* d_out, int out_size)
{
    const float* rf = (const float*)d_in[0];   // [B, Nc, Ns, K]
    const float* g  = (const float*)d_in[1];   // [B, Nz, Nx, 3]
    const float* pr = (const float*)d_in[2];   // [B, Nc, 3]
    const float* p  = (const float*)d_in[3];   // [B, 4]
    float* out = (float*)d_out;                // [B, Nz, Nx, K]

    cudaFuncSetAttribute(das_beamform_kernel,
                         cudaFuncAttributeMaxDynamicSharedMemorySize, SMEM_BYTES);

    // 1) convert rf to fp16 scratch (2 sample-rows per thread)
    int rows = NB * NC * NS;   // 524288
    convert_rf_kernel<<<rows / 2 / THREADS, THREADS>>>((const float4*)rf);

    // 2) beamform per (tile, batch, channel-slice)
    dim3 grid(TILES, NB, SPLIT);
    das_beamform_kernel<<<grid, THREADS, SMEM_BYTES>>>(g, pr, p);

    // 3) reduce partials
    int n4 = NB * MPX;         // 131072 float4s
    reduce_kernel<<<n4 / THREADS, THREADS>>>((float4*)out);
}